// round 13
// baseline (speedup 1.0000x reference)
#include <cuda_runtime.h>
#include <cstdint>

// ---------------------------------------------------------------------------
// W8A8B32O32 Linear: D[m,n] = round(alpha * sum_k x[m,k]*W[n,k] + beta*bias[n])
// M=8192, K=4096, N=4096. Inputs int32 (int8-range). OUTPUT dtype FLOAT32.
//
// ROUND 13: resubmission of rounds 11/12 (broker infra failed; never ran).
// Audited for hang/OOB/alignment — clean.
//   - ldmatrix.x4 fragment loads (48 LDS -> 12 ldmatrix per warp per k-iter)
//   - single __syncthreads per k-iter (cutlass multistage ordering), 4 stages
// ---------------------------------------------------------------------------

#define M_DIM 8192
#define N_DIM 4096
#define K_DIM 4096
#define BM 128
#define BN 128
#define BK 64
#define KI (K_DIM / BK)      // 64
#define STAGES 4

#define ROWB 80                            // 64 data bytes + 16 pad (20-bank stride)
#define TILE_BYTES (128 * ROWB)            // 10240 per operand
#define STAGE_BYTES (2 * TILE_BYTES)       // 20480
#define SMEM_TOTAL (STAGES * STAGE_BYTES)  // 81920

// int8 scratch (device globals: allocation-guard safe)
__device__ __align__(1024) int8_t g_x8[(size_t)M_DIM * K_DIM];   // 32 MB
__device__ __align__(1024) int8_t g_w8[(size_t)N_DIM * K_DIM];   // 16 MB

static __device__ __forceinline__ uint32_t smem_u32(const void* p) {
    uint32_t r;
    asm("{ .reg .u64 t; cvta.to.shared.u64 t, %1; cvt.u32.u64 %0, t; }" : "=r"(r) : "l"(p));
    return r;
}

// ---------------------------------------------------------------------------
// Pack kernel: 16 int32 -> 16 int8 per thread
// ---------------------------------------------------------------------------
__global__ void __launch_bounds__(256) pack_i32_to_i8(const int* __restrict__ src,
                                                      int8_t* __restrict__ dst, int n16) {
    int i = blockIdx.x * blockDim.x + threadIdx.x;
    if (i >= n16) return;
    const int4* s = reinterpret_cast<const int4*>(src) + (size_t)i * 4;
    int4 v0 = s[0], v1 = s[1], v2 = s[2], v3 = s[3];
    auto pk = [](int4 v) -> uint32_t {
        uint32_t lo = __byte_perm((uint32_t)v.x, (uint32_t)v.y, 0x0040);
        uint32_t hi = __byte_perm((uint32_t)v.z, (uint32_t)v.w, 0x0040);
        return __byte_perm(lo, hi, 0x5410);
    };
    uint4 o = make_uint4(pk(v0), pk(v1), pk(v2), pk(v3));
    reinterpret_cast<uint4*>(dst)[i] = o;
}

// ---------------------------------------------------------------------------
// GEMM: m16n8k32 IMMA, 128x128 CTA tile, 8 warps of 64x32, 4-stage cp.async,
// ldmatrix fragment loads, single barrier per k-iter.
// ---------------------------------------------------------------------------
__global__ void __launch_bounds__(256, 1) gemm_i8_imma(
    const int8_t* __restrict__ A8, const int8_t* __restrict__ B8,
    const int* __restrict__ bias, const float* __restrict__ alphap,
    const float* __restrict__ betap, float* __restrict__ out) {
    extern __shared__ char smem[];
    const uint32_t sbase = smem_u32(smem);
    const int tid = threadIdx.x;
    const int wid = tid >> 5;
    const int lane = tid & 31;
    const int warp_m = wid & 1;          // 2 warp rows x 64
    const int warp_n = wid >> 1;         // 4 warp cols x 32
    const int m0 = blockIdx.y * BM;
    const int n0 = blockIdx.x * BN;

    const int8_t* ga = A8 + (size_t)m0 * K_DIM;
    const int8_t* gb = B8 + (size_t)n0 * K_DIM;

    // cp.async mapping: 512 x 16B chunks per operand per stage, 2 each/thread
    const int ld_row0 = tid >> 2;              // 0..63
    const int ld_chunk = (tid & 3) * 16;       // 0/16/32/48
    const uint32_t so0 = (uint32_t)(ld_row0 * ROWB + ld_chunk);
    const uint32_t so1 = (uint32_t)((ld_row0 + 64) * ROWB + ld_chunk);

    auto load_stage = [&](int st, int kiter) {
        const int koff = kiter * BK;
        const uint32_t sA = sbase + st * STAGE_BYTES;
        const uint32_t sB = sA + TILE_BYTES;
        const int8_t* gpa0 = ga + (size_t)ld_row0 * K_DIM + koff + ld_chunk;
        const int8_t* gpa1 = gpa0 + (size_t)64 * K_DIM;
        const int8_t* gpb0 = gb + (size_t)ld_row0 * K_DIM + koff + ld_chunk;
        const int8_t* gpb1 = gpb0 + (size_t)64 * K_DIM;
        asm volatile("cp.async.cg.shared.global [%0], [%1], 16;" :: "r"(sA + so0), "l"(gpa0));
        asm volatile("cp.async.cg.shared.global [%0], [%1], 16;" :: "r"(sA + so1), "l"(gpa1));
        asm volatile("cp.async.cg.shared.global [%0], [%1], 16;" :: "r"(sB + so0), "l"(gpb0));
        asm volatile("cp.async.cg.shared.global [%0], [%1], 16;" :: "r"(sB + so1), "l"(gpb1));
    };

    // ldmatrix lane-address offsets (within a tile).
    // A (x4): m0=(rows0-7,k0-15) m1=(rows8-15,k0-15) m2=(rows0-7,k16-31) m3=(rows8-15,k16-31)
    const uint32_t a_lane_off =
        (uint32_t)((warp_m * 64 + (lane & 15)) * ROWB + ((lane >> 4) * 16));
    // B (x4): m0=(n0-7,k0-15) m1=(n0-7,k16-31) m2=(n8-15,k0-15) m3=(n8-15,k16-31)
    const uint32_t b_lane_off =
        (uint32_t)((warp_n * 32 + (lane & 7) + ((lane >> 4) & 1) * 8) * ROWB +
                   (((lane >> 3) & 1) * 16));

    int acc[4][4][4];
    #pragma unroll
    for (int i = 0; i < 4; i++)
        #pragma unroll
        for (int j = 0; j < 4; j++)
            #pragma unroll
            for (int r = 0; r < 4; r++) acc[i][j][r] = 0;

    // prologue: fill stages 0..STAGES-2 (groups 0..STAGES-2)
    #pragma unroll
    for (int s = 0; s < STAGES - 1; s++) {
        load_stage(s, s);
        asm volatile("cp.async.commit_group;" ::: "memory");
    }

    for (int k = 0; k < KI; k++) {
        // complete group k (leave STAGES-2 in flight)
        asm volatile("cp.async.wait_group %0;" :: "n"(STAGES - 2) : "memory");
        __syncthreads();

        // issue chunk k+STAGES-1 into stage (k+STAGES-1)%STAGES.
        // That stage was computed at iter k-1; every warp passed the barrier
        // above, so it is safe to overwrite. Always commit (empty at tail)
        // to keep group numbering aligned.
        if (k + STAGES - 1 < KI)
            load_stage((k + STAGES - 1) & (STAGES - 1), k + STAGES - 1);
        asm volatile("cp.async.commit_group;" ::: "memory");

        const int st = k & (STAGES - 1);
        const uint32_t sA = sbase + st * STAGE_BYTES;
        const uint32_t sB = sA + TILE_BYTES;

        #pragma unroll
        for (int ks = 0; ks < 2; ks++) {               // two k32 steps per BK=64
            const uint32_t ko = (uint32_t)(ks * 32);
            uint32_t a[4][4];
            #pragma unroll
            for (int mi = 0; mi < 4; mi++) {
                uint32_t addr = sA + a_lane_off + (uint32_t)(mi * 16 * ROWB) + ko;
                asm volatile("ldmatrix.sync.aligned.m8n8.x4.shared.b16 {%0,%1,%2,%3}, [%4];"
                             : "=r"(a[mi][0]), "=r"(a[mi][1]), "=r"(a[mi][2]), "=r"(a[mi][3])
                             : "r"(addr));
            }
            uint32_t b[2][4];
            #pragma unroll
            for (int bi = 0; bi < 2; bi++) {
                uint32_t addr = sB + b_lane_off + (uint32_t)(bi * 16 * ROWB) + ko;
                asm volatile("ldmatrix.sync.aligned.m8n8.x4.shared.b16 {%0,%1,%2,%3}, [%4];"
                             : "=r"(b[bi][0]), "=r"(b[bi][1]), "=r"(b[bi][2]), "=r"(b[bi][3])
                             : "r"(addr));
            }
            #pragma unroll
            for (int mi = 0; mi < 4; mi++) {
                #pragma unroll
                for (int ni = 0; ni < 4; ni++) {
                    uint32_t b0 = b[ni >> 1][(ni & 1) * 2 + 0];
                    uint32_t b1 = b[ni >> 1][(ni & 1) * 2 + 1];
                    asm volatile(
                        "mma.sync.aligned.m16n8k32.row.col.s32.s8.s8.s32 "
                        "{%0,%1,%2,%3}, {%4,%5,%6,%7}, {%8,%9}, {%0,%1,%2,%3};"
                        : "+r"(acc[mi][ni][0]), "+r"(acc[mi][ni][1]),
                          "+r"(acc[mi][ni][2]), "+r"(acc[mi][ni][3])
                        : "r"(a[mi][0]), "r"(a[mi][1]), "r"(a[mi][2]), "r"(a[mi][3]),
                          "r"(b0), "r"(b1));
                }
            }
        }
    }

    // ------------------------- epilogue (float32 out) -------------------
    const float av = *alphap;
    const float bv = *betap;
    const int mrow = m0 + warp_m * 64 + (lane >> 2);
    const int ncol = n0 + warp_n * 32 + 2 * (lane & 3);
    #pragma unroll
    for (int mi = 0; mi < 4; mi++) {
        #pragma unroll
        for (int ni = 0; ni < 4; ni++) {
            const int n = ncol + ni * 8;
            const float bb0 = __fmul_rn(bv, (float)bias[n + 0]);
            const float bb1 = __fmul_rn(bv, (float)bias[n + 1]);
            float2 o0, o1;
            o0.x = (float)__float2int_rn(__fadd_rn(__fmul_rn(av, (float)acc[mi][ni][0]), bb0));
            o0.y = (float)__float2int_rn(__fadd_rn(__fmul_rn(av, (float)acc[mi][ni][1]), bb1));
            o1.x = (float)__float2int_rn(__fadd_rn(__fmul_rn(av, (float)acc[mi][ni][2]), bb0));
            o1.y = (float)__float2int_rn(__fadd_rn(__fmul_rn(av, (float)acc[mi][ni][3]), bb1));
            const size_t r0 = (size_t)(mrow + mi * 16) * N_DIM + n;
            const size_t r1 = r0 + (size_t)8 * N_DIM;
            *reinterpret_cast<float2*>(out + r0) = o0;
            *reinterpret_cast<float2*>(out + r1) = o1;
        }
    }
}

// ---------------------------------------------------------------------------
extern "C" void kernel_launch(void* const* d_in, const int* in_sizes, int n_in,
                              void* d_out, int out_size) {
    // Bind inputs BY SIZE (robust to metadata ordering).
    const int* x = nullptr;
    const int* w = nullptr;
    const int* bias = nullptr;
    const float* alpha = nullptr;
    const float* beta = nullptr;
    for (int i = 0; i < n_in; i++) {
        const long sz = (long)in_sizes[i];
        if (sz == (long)M_DIM * K_DIM) x = (const int*)d_in[i];
        else if (sz == (long)N_DIM * K_DIM) w = (const int*)d_in[i];
        else if (sz == N_DIM) bias = (const int*)d_in[i];
        else if (sz == 1) {
            if (!alpha) alpha = (const float*)d_in[i];
            else beta = (const float*)d_in[i];
        }
    }
    float* out = (float*)d_out;

    void* px = nullptr;
    void* pw = nullptr;
    cudaGetSymbolAddress(&px, g_x8);
    cudaGetSymbolAddress(&pw, g_w8);

    const int nx16 = (M_DIM * (K_DIM / 16));
    const int nw16 = (N_DIM * (K_DIM / 16));
    pack_i32_to_i8<<<(nx16 + 255) / 256, 256>>>(x, (int8_t*)px, nx16);
    pack_i32_to_i8<<<(nw16 + 255) / 256, 256>>>(w, (int8_t*)pw, nw16);

    cudaFuncSetAttribute(gemm_i8_imma,
                         cudaFuncAttributeMaxDynamicSharedMemorySize, SMEM_TOTAL);
    dim3 grid(N_DIM / BN, M_DIM / BM);   // (32, 64)
    gemm_i8_imma<<<grid, 256, SMEM_TOTAL>>>((const int8_t*)px, (const int8_t*)pw,
                                            bias, alpha, beta, out);
}

// round 14
// speedup vs baseline: 1.1584x; 1.1584x over previous
#include <cuda_runtime.h>
#include <cstdint>

// ---------------------------------------------------------------------------
// W8A8B32O32 Linear: D[m,n] = round(alpha * sum_k x[m,k]*W[n,k] + beta*bias[n])
// M=8192, K=4096, N=4096. Inputs int32 (int8-range). OUTPUT dtype FLOAT32.
//
// ROUND 14: round-13 regression diagnosed as occupancy loss (regs > 128 ->
// 1 CTA/SM). Fix: __launch_bounds__(256, 2) + STAGES=3 (smem 61440).
// Keep ldmatrix.x4 fragments (lane maps confirmed by rel_err=0) and
// single-barrier multistage ordering.
// ---------------------------------------------------------------------------

#define M_DIM 8192
#define N_DIM 4096
#define K_DIM 4096
#define BM 128
#define BN 128
#define BK 64
#define KI (K_DIM / BK)      // 64
#define STAGES 3

#define ROWB 80                            // 64 data bytes + 16 pad (20-bank stride)
#define TILE_BYTES (128 * ROWB)            // 10240 per operand
#define STAGE_BYTES (2 * TILE_BYTES)       // 20480
#define SMEM_TOTAL (STAGES * STAGE_BYTES)  // 61440 -> 2 CTAs/SM by smem

// int8 scratch (device globals: allocation-guard safe)
__device__ __align__(1024) int8_t g_x8[(size_t)M_DIM * K_DIM];   // 32 MB
__device__ __align__(1024) int8_t g_w8[(size_t)N_DIM * K_DIM];   // 16 MB

static __device__ __forceinline__ uint32_t smem_u32(const void* p) {
    uint32_t r;
    asm("{ .reg .u64 t; cvta.to.shared.u64 t, %1; cvt.u32.u64 %0, t; }" : "=r"(r) : "l"(p));
    return r;
}

// ---------------------------------------------------------------------------
// Pack kernel: 16 int32 -> 16 int8 per thread
// ---------------------------------------------------------------------------
__global__ void __launch_bounds__(256) pack_i32_to_i8(const int* __restrict__ src,
                                                      int8_t* __restrict__ dst, int n16) {
    int i = blockIdx.x * blockDim.x + threadIdx.x;
    if (i >= n16) return;
    const int4* s = reinterpret_cast<const int4*>(src) + (size_t)i * 4;
    int4 v0 = s[0], v1 = s[1], v2 = s[2], v3 = s[3];
    auto pk = [](int4 v) -> uint32_t {
        uint32_t lo = __byte_perm((uint32_t)v.x, (uint32_t)v.y, 0x0040);
        uint32_t hi = __byte_perm((uint32_t)v.z, (uint32_t)v.w, 0x0040);
        return __byte_perm(lo, hi, 0x5410);
    };
    uint4 o = make_uint4(pk(v0), pk(v1), pk(v2), pk(v3));
    reinterpret_cast<uint4*>(dst)[i] = o;
}

// ---------------------------------------------------------------------------
// GEMM: m16n8k32 IMMA, 128x128 CTA tile, 8 warps of 64x32, 3-stage cp.async,
// ldmatrix fragments, single barrier per k-iter, forced 2 CTAs/SM.
// ---------------------------------------------------------------------------
__global__ void __launch_bounds__(256, 2) gemm_i8_imma(
    const int8_t* __restrict__ A8, const int8_t* __restrict__ B8,
    const int* __restrict__ bias, const float* __restrict__ alphap,
    const float* __restrict__ betap, float* __restrict__ out) {
    extern __shared__ char smem[];
    const uint32_t sbase = smem_u32(smem);
    const int tid = threadIdx.x;
    const int wid = tid >> 5;
    const int lane = tid & 31;
    const int warp_m = wid & 1;          // 2 warp rows x 64
    const int warp_n = wid >> 1;         // 4 warp cols x 32
    const int m0 = blockIdx.y * BM;
    const int n0 = blockIdx.x * BN;

    const int8_t* ga = A8 + (size_t)m0 * K_DIM;
    const int8_t* gb = B8 + (size_t)n0 * K_DIM;

    // cp.async mapping: 512 x 16B chunks per operand per stage, 2 each/thread
    const int ld_row0 = tid >> 2;              // 0..63
    const int ld_chunk = (tid & 3) * 16;       // 0/16/32/48
    const uint32_t so0 = (uint32_t)(ld_row0 * ROWB + ld_chunk);
    const uint32_t so1 = (uint32_t)((ld_row0 + 64) * ROWB + ld_chunk);

    auto load_stage = [&](int st, int kiter) {
        const int koff = kiter * BK;
        const uint32_t sA = sbase + st * STAGE_BYTES;
        const uint32_t sB = sA + TILE_BYTES;
        const int8_t* gpa0 = ga + (size_t)ld_row0 * K_DIM + koff + ld_chunk;
        const int8_t* gpa1 = gpa0 + (size_t)64 * K_DIM;
        const int8_t* gpb0 = gb + (size_t)ld_row0 * K_DIM + koff + ld_chunk;
        const int8_t* gpb1 = gpb0 + (size_t)64 * K_DIM;
        asm volatile("cp.async.cg.shared.global [%0], [%1], 16;" :: "r"(sA + so0), "l"(gpa0));
        asm volatile("cp.async.cg.shared.global [%0], [%1], 16;" :: "r"(sA + so1), "l"(gpa1));
        asm volatile("cp.async.cg.shared.global [%0], [%1], 16;" :: "r"(sB + so0), "l"(gpb0));
        asm volatile("cp.async.cg.shared.global [%0], [%1], 16;" :: "r"(sB + so1), "l"(gpb1));
    };

    // ldmatrix lane-address offsets (within a tile) — maps confirmed (rel_err=0).
    const uint32_t a_lane_off =
        (uint32_t)((warp_m * 64 + (lane & 15)) * ROWB + ((lane >> 4) * 16));
    const uint32_t b_lane_off =
        (uint32_t)((warp_n * 32 + (lane & 7) + ((lane >> 4) & 1) * 8) * ROWB +
                   (((lane >> 3) & 1) * 16));

    int acc[4][4][4];
    #pragma unroll
    for (int i = 0; i < 4; i++)
        #pragma unroll
        for (int j = 0; j < 4; j++)
            #pragma unroll
            for (int r = 0; r < 4; r++) acc[i][j][r] = 0;

    // prologue: fill stages 0..STAGES-2 (groups 0..STAGES-2)
    #pragma unroll
    for (int s = 0; s < STAGES - 1; s++) {
        load_stage(s, s);
        asm volatile("cp.async.commit_group;" ::: "memory");
    }

    for (int k = 0; k < KI; k++) {
        // complete group k (leave up to STAGES-2 in flight)
        asm volatile("cp.async.wait_group %0;" :: "n"(STAGES - 2) : "memory");
        __syncthreads();

        // issue chunk k+STAGES-1 into its stage; that stage was computed at
        // iter k-1 and all warps passed the barrier above.
        if (k + STAGES - 1 < KI) {
            int st_next = (k + STAGES - 1) % STAGES;
            load_stage(st_next, k + STAGES - 1);
        }
        asm volatile("cp.async.commit_group;" ::: "memory");

        const int st = k % STAGES;
        const uint32_t sA = sbase + st * STAGE_BYTES;
        const uint32_t sB = sA + TILE_BYTES;

        #pragma unroll
        for (int ks = 0; ks < 2; ks++) {               // two k32 steps per BK=64
            const uint32_t ko = (uint32_t)(ks * 32);
            uint32_t a[4][4];
            #pragma unroll
            for (int mi = 0; mi < 4; mi++) {
                uint32_t addr = sA + a_lane_off + (uint32_t)(mi * 16 * ROWB) + ko;
                asm volatile("ldmatrix.sync.aligned.m8n8.x4.shared.b16 {%0,%1,%2,%3}, [%4];"
                             : "=r"(a[mi][0]), "=r"(a[mi][1]), "=r"(a[mi][2]), "=r"(a[mi][3])
                             : "r"(addr));
            }
            uint32_t b[2][4];
            #pragma unroll
            for (int bi = 0; bi < 2; bi++) {
                uint32_t addr = sB + b_lane_off + (uint32_t)(bi * 16 * ROWB) + ko;
                asm volatile("ldmatrix.sync.aligned.m8n8.x4.shared.b16 {%0,%1,%2,%3}, [%4];"
                             : "=r"(b[bi][0]), "=r"(b[bi][1]), "=r"(b[bi][2]), "=r"(b[bi][3])
                             : "r"(addr));
            }
            #pragma unroll
            for (int mi = 0; mi < 4; mi++) {
                #pragma unroll
                for (int ni = 0; ni < 4; ni++) {
                    uint32_t b0 = b[ni >> 1][(ni & 1) * 2 + 0];
                    uint32_t b1 = b[ni >> 1][(ni & 1) * 2 + 1];
                    asm volatile(
                        "mma.sync.aligned.m16n8k32.row.col.s32.s8.s8.s32 "
                        "{%0,%1,%2,%3}, {%4,%5,%6,%7}, {%8,%9}, {%0,%1,%2,%3};"
                        : "+r"(acc[mi][ni][0]), "+r"(acc[mi][ni][1]),
                          "+r"(acc[mi][ni][2]), "+r"(acc[mi][ni][3])
                        : "r"(a[mi][0]), "r"(a[mi][1]), "r"(a[mi][2]), "r"(a[mi][3]),
                          "r"(b0), "r"(b1));
                }
            }
        }
    }

    // ------------------------- epilogue (float32 out) -------------------
    const float av = *alphap;
    const float bv = *betap;
    const int mrow = m0 + warp_m * 64 + (lane >> 2);
    const int ncol = n0 + warp_n * 32 + 2 * (lane & 3);
    #pragma unroll
    for (int mi = 0; mi < 4; mi++) {
        #pragma unroll
        for (int ni = 0; ni < 4; ni++) {
            const int n = ncol + ni * 8;
            const float bb0 = __fmul_rn(bv, (float)bias[n + 0]);
            const float bb1 = __fmul_rn(bv, (float)bias[n + 1]);
            float2 o0, o1;
            o0.x = (float)__float2int_rn(__fadd_rn(__fmul_rn(av, (float)acc[mi][ni][0]), bb0));
            o0.y = (float)__float2int_rn(__fadd_rn(__fmul_rn(av, (float)acc[mi][ni][1]), bb1));
            o1.x = (float)__float2int_rn(__fadd_rn(__fmul_rn(av, (float)acc[mi][ni][2]), bb0));
            o1.y = (float)__float2int_rn(__fadd_rn(__fmul_rn(av, (float)acc[mi][ni][3]), bb1));
            const size_t r0 = (size_t)(mrow + mi * 16) * N_DIM + n;
            const size_t r1 = r0 + (size_t)8 * N_DIM;
            *reinterpret_cast<float2*>(out + r0) = o0;
            *reinterpret_cast<float2*>(out + r1) = o1;
        }
    }
}

// ---------------------------------------------------------------------------
extern "C" void kernel_launch(void* const* d_in, const int* in_sizes, int n_in,
                              void* d_out, int out_size) {
    // Bind inputs BY SIZE (robust to metadata ordering).
    const int* x = nullptr;
    const int* w = nullptr;
    const int* bias = nullptr;
    const float* alpha = nullptr;
    const float* beta = nullptr;
    for (int i = 0; i < n_in; i++) {
        const long sz = (long)in_sizes[i];
        if (sz == (long)M_DIM * K_DIM) x = (const int*)d_in[i];
        else if (sz == (long)N_DIM * K_DIM) w = (const int*)d_in[i];
        else if (sz == N_DIM) bias = (const int*)d_in[i];
        else if (sz == 1) {
            if (!alpha) alpha = (const float*)d_in[i];
            else beta = (const float*)d_in[i];
        }
    }
    float* out = (float*)d_out;

    void* px = nullptr;
    void* pw = nullptr;
    cudaGetSymbolAddress(&px, g_x8);
    cudaGetSymbolAddress(&pw, g_w8);

    const int nx16 = (M_DIM * (K_DIM / 16));
    const int nw16 = (N_DIM * (K_DIM / 16));
    pack_i32_to_i8<<<(nx16 + 255) / 256, 256>>>(x, (int8_t*)px, nx16);
    pack_i32_to_i8<<<(nw16 + 255) / 256, 256>>>(w, (int8_t*)pw, nw16);

    cudaFuncSetAttribute(gemm_i8_imma,
                         cudaFuncAttributeMaxDynamicSharedMemorySize, SMEM_TOTAL);
    dim3 grid(N_DIM / BN, M_DIM / BM);   // (32, 64)
    gemm_i8_imma<<<grid, 256, SMEM_TOTAL>>>((const int8_t*)px, (const int8_t*)pw,
                                            bias, alpha, beta, out);
}

// round 17
// speedup vs baseline: 1.4419x; 1.2448x over previous
#include <cuda_runtime.h>
#include <cstdint>

// ---------------------------------------------------------------------------
// W8A8B32O32 Linear: D[m,n] = round(alpha * sum_k x[m,k]*W[n,k] + beta*bias[n])
// M=8192, K=4096, N=4096. Inputs int32 (int8-range). OUTPUT dtype FLOAT32.
//
// ROUND 17: resubmission of round 16 (broker infra failed twice; never ran).
// 64x64 warp tiles (4 warps, 128 threads): halves LDSM bytes per MMA.
// Loader mapping fixed vs round 15: rows tid>>2 + 32i, chunk (tid&3)*16,
// every address within the 64B data row. 3-stage cp.async, single barrier,
// 2 CTAs/SM.
// ---------------------------------------------------------------------------

#define M_DIM 8192
#define N_DIM 4096
#define K_DIM 4096
#define BM 128
#define BN 128
#define BK 64
#define KI (K_DIM / BK)      // 64
#define STAGES 3
#define NTHREADS 128

#define ROWB 80                            // 64 data bytes + 16 pad (20-bank stride)
#define TILE_BYTES (128 * ROWB)            // 10240 per operand
#define STAGE_BYTES (2 * TILE_BYTES)       // 20480
#define SMEM_TOTAL (STAGES * STAGE_BYTES)  // 61440 -> 2 CTAs/SM by smem

// int8 scratch (device globals: allocation-guard safe)
__device__ __align__(1024) int8_t g_x8[(size_t)M_DIM * K_DIM];   // 32 MB
__device__ __align__(1024) int8_t g_w8[(size_t)N_DIM * K_DIM];   // 16 MB

static __device__ __forceinline__ uint32_t smem_u32(const void* p) {
    uint32_t r;
    asm("{ .reg .u64 t; cvta.to.shared.u64 t, %1; cvt.u32.u64 %0, t; }" : "=r"(r) : "l"(p));
    return r;
}

// ---------------------------------------------------------------------------
// Pack kernel: 16 int32 -> 16 int8 per thread
// ---------------------------------------------------------------------------
__global__ void __launch_bounds__(256) pack_i32_to_i8(const int* __restrict__ src,
                                                      int8_t* __restrict__ dst, int n16) {
    int i = blockIdx.x * blockDim.x + threadIdx.x;
    if (i >= n16) return;
    const int4* s = reinterpret_cast<const int4*>(src) + (size_t)i * 4;
    int4 v0 = s[0], v1 = s[1], v2 = s[2], v3 = s[3];
    auto pk = [](int4 v) -> uint32_t {
        uint32_t lo = __byte_perm((uint32_t)v.x, (uint32_t)v.y, 0x0040);
        uint32_t hi = __byte_perm((uint32_t)v.z, (uint32_t)v.w, 0x0040);
        return __byte_perm(lo, hi, 0x5410);
    };
    uint4 o = make_uint4(pk(v0), pk(v1), pk(v2), pk(v3));
    reinterpret_cast<uint4*>(dst)[i] = o;
}

// ---------------------------------------------------------------------------
// GEMM: m16n8k32 IMMA, 128x128 CTA tile, 4 warps of 64x64, 3-stage cp.async,
// ldmatrix fragments, single barrier per k-iter, 2 CTAs/SM.
// ---------------------------------------------------------------------------
__global__ void __launch_bounds__(NTHREADS, 2) gemm_i8_imma(
    const int8_t* __restrict__ A8, const int8_t* __restrict__ B8,
    const int* __restrict__ bias, const float* __restrict__ alphap,
    const float* __restrict__ betap, float* __restrict__ out) {
    extern __shared__ char smem[];
    const uint32_t sbase = smem_u32(smem);
    const int tid = threadIdx.x;
    const int wid = tid >> 5;            // 0..3
    const int lane = tid & 31;
    const int warp_m = wid & 1;          // 2 warp rows x 64
    const int warp_n = wid >> 1;         // 2 warp cols x 64
    const int m0 = blockIdx.y * BM;
    const int n0 = blockIdx.x * BN;

    const int8_t* ga = A8 + (size_t)m0 * K_DIM;
    const int8_t* gb = B8 + (size_t)n0 * K_DIM;

    // cp.async mapping: 512 x 16B chunks per operand per stage.
    // 128 threads: rows tid>>2 + 32*i (i=0..3), chunk (tid&3)*16 in [0,64).
    const int ld_row0 = tid >> 2;              // 0..31
    const int ld_chunk = (tid & 3) * 16;       // 0/16/32/48
    auto load_stage = [&](int st, int kiter) {
        const int koff = kiter * BK;
        const uint32_t sA = sbase + st * STAGE_BYTES;
        const uint32_t sB = sA + TILE_BYTES;
        #pragma unroll
        for (int i = 0; i < 4; i++) {
            const int row = ld_row0 + i * 32;                  // 0..127
            const uint32_t so = (uint32_t)(row * ROWB + ld_chunk);
            const int8_t* gpa = ga + (size_t)row * K_DIM + koff + ld_chunk;
            const int8_t* gpb = gb + (size_t)row * K_DIM + koff + ld_chunk;
            asm volatile("cp.async.cg.shared.global [%0], [%1], 16;" :: "r"(sA + so), "l"(gpa));
            asm volatile("cp.async.cg.shared.global [%0], [%1], 16;" :: "r"(sB + so), "l"(gpb));
        }
    };

    // ldmatrix lane-address offsets (within a tile) — maps confirmed round 13.
    const uint32_t a_lane_off =
        (uint32_t)((warp_m * 64 + (lane & 15)) * ROWB + ((lane >> 4) * 16));
    const uint32_t b_lane_off =
        (uint32_t)((warp_n * 64 + (lane & 7) + ((lane >> 4) & 1) * 8) * ROWB +
                   (((lane >> 3) & 1) * 16));

    int acc[4][8][4];
    #pragma unroll
    for (int i = 0; i < 4; i++)
        #pragma unroll
        for (int j = 0; j < 8; j++)
            #pragma unroll
            for (int r = 0; r < 4; r++) acc[i][j][r] = 0;

    // prologue: fill stages 0..STAGES-2
    #pragma unroll
    for (int s = 0; s < STAGES - 1; s++) {
        load_stage(s, s);
        asm volatile("cp.async.commit_group;" ::: "memory");
    }

    for (int k = 0; k < KI; k++) {
        asm volatile("cp.async.wait_group %0;" :: "n"(STAGES - 2) : "memory");
        __syncthreads();

        if (k + STAGES - 1 < KI) {
            int st_next = (k + STAGES - 1) % STAGES;
            load_stage(st_next, k + STAGES - 1);
        }
        asm volatile("cp.async.commit_group;" ::: "memory");

        const int st = k % STAGES;
        const uint32_t sA = sbase + st * STAGE_BYTES;
        const uint32_t sB = sA + TILE_BYTES;

        #pragma unroll
        for (int ks = 0; ks < 2; ks++) {               // two k32 steps per BK=64
            const uint32_t ko = (uint32_t)(ks * 32);
            uint32_t a[4][4];
            #pragma unroll
            for (int mi = 0; mi < 4; mi++) {
                uint32_t addr = sA + a_lane_off + (uint32_t)(mi * 16 * ROWB) + ko;
                asm volatile("ldmatrix.sync.aligned.m8n8.x4.shared.b16 {%0,%1,%2,%3}, [%4];"
                             : "=r"(a[mi][0]), "=r"(a[mi][1]), "=r"(a[mi][2]), "=r"(a[mi][3])
                             : "r"(addr));
            }
            uint32_t b[4][4];
            #pragma unroll
            for (int bi = 0; bi < 4; bi++) {           // 4 x (n16 x k32)
                uint32_t addr = sB + b_lane_off + (uint32_t)(bi * 16 * ROWB) + ko;
                asm volatile("ldmatrix.sync.aligned.m8n8.x4.shared.b16 {%0,%1,%2,%3}, [%4];"
                             : "=r"(b[bi][0]), "=r"(b[bi][1]), "=r"(b[bi][2]), "=r"(b[bi][3])
                             : "r"(addr));
            }
            #pragma unroll
            for (int mi = 0; mi < 4; mi++) {
                #pragma unroll
                for (int ni = 0; ni < 8; ni++) {
                    uint32_t b0 = b[ni >> 1][(ni & 1) * 2 + 0];
                    uint32_t b1 = b[ni >> 1][(ni & 1) * 2 + 1];
                    asm volatile(
                        "mma.sync.aligned.m16n8k32.row.col.s32.s8.s8.s32 "
                        "{%0,%1,%2,%3}, {%4,%5,%6,%7}, {%8,%9}, {%0,%1,%2,%3};"
                        : "+r"(acc[mi][ni][0]), "+r"(acc[mi][ni][1]),
                          "+r"(acc[mi][ni][2]), "+r"(acc[mi][ni][3])
                        : "r"(a[mi][0]), "r"(a[mi][1]), "r"(a[mi][2]), "r"(a[mi][3]),
                          "r"(b0), "r"(b1));
                }
            }
        }
    }

    // ------------------------- epilogue (float32 out) -------------------
    const float av = *alphap;
    const float bv = *betap;
    const int mrow = m0 + warp_m * 64 + (lane >> 2);
    const int ncol = n0 + warp_n * 64 + 2 * (lane & 3);
    #pragma unroll
    for (int mi = 0; mi < 4; mi++) {
        #pragma unroll
        for (int ni = 0; ni < 8; ni++) {
            const int n = ncol + ni * 8;
            const float bb0 = __fmul_rn(bv, (float)bias[n + 0]);
            const float bb1 = __fmul_rn(bv, (float)bias[n + 1]);
            float2 o0, o1;
            o0.x = (float)__float2int_rn(__fadd_rn(__fmul_rn(av, (float)acc[mi][ni][0]), bb0));
            o0.y = (float)__float2int_rn(__fadd_rn(__fmul_rn(av, (float)acc[mi][ni][1]), bb1));
            o1.x = (float)__float2int_rn(__fadd_rn(__fmul_rn(av, (float)acc[mi][ni][2]), bb0));
            o1.y = (float)__float2int_rn(__fadd_rn(__fmul_rn(av, (float)acc[mi][ni][3]), bb1));
            const size_t r0 = (size_t)(mrow + mi * 16) * N_DIM + n;
            const size_t r1 = r0 + (size_t)8 * N_DIM;
            *reinterpret_cast<float2*>(out + r0) = o0;
            *reinterpret_cast<float2*>(out + r1) = o1;
        }
    }
}

// ---------------------------------------------------------------------------
extern "C" void kernel_launch(void* const* d_in, const int* in_sizes, int n_in,
                              void* d_out, int out_size) {
    // Bind inputs BY SIZE (robust to metadata ordering).
    const int* x = nullptr;
    const int* w = nullptr;
    const int* bias = nullptr;
    const float* alpha = nullptr;
    const float* beta = nullptr;
    for (int i = 0; i < n_in; i++) {
        const long sz = (long)in_sizes[i];
        if (sz == (long)M_DIM * K_DIM) x = (const int*)d_in[i];
        else if (sz == (long)N_DIM * K_DIM) w = (const int*)d_in[i];
        else if (sz == N_DIM) bias = (const int*)d_in[i];
        else if (sz == 1) {
            if (!alpha) alpha = (const float*)d_in[i];
            else beta = (const float*)d_in[i];
        }
    }
    float* out = (float*)d_out;

    void* px = nullptr;
    void* pw = nullptr;
    cudaGetSymbolAddress(&px, g_x8);
    cudaGetSymbolAddress(&pw, g_w8);

    const int nx16 = (M_DIM * (K_DIM / 16));
    const int nw16 = (N_DIM * (K_DIM / 16));
    pack_i32_to_i8<<<(nx16 + 255) / 256, 256>>>(x, (int8_t*)px, nx16);
    pack_i32_to_i8<<<(nw16 + 255) / 256, 256>>>(w, (int8_t*)pw, nw16);

    cudaFuncSetAttribute(gemm_i8_imma,
                         cudaFuncAttributeMaxDynamicSharedMemorySize, SMEM_TOTAL);
    dim3 grid(N_DIM / BN, M_DIM / BM);   // (32, 64)
    gemm_i8_imma<<<grid, NTHREADS, SMEM_TOTAL>>>((const int8_t*)px, (const int8_t*)pw,
                                                 bias, alpha, beta, out);
}